// round 1
// baseline (speedup 1.0000x reference)
#include <cuda_runtime.h>
#include <cuda_bf16.h>
#include <math.h>

#define Bsz 32
#define Ssz 576
#define Dsz 768
#define Gsz 24
#define Mrows (Bsz*Ssz)   // 18432

// Scratch (device globals: allocation-free rule)
__device__ float g_q[Mrows*Dsz];
__device__ float g_k[Mrows*Dsz];
__device__ float g_v[Mrows*Dsz];
__device__ float g_sample[Mrows*2];

// ---------------------------------------------------------------------------
// Kernel 1: fused QKV projection.  C(18432 x 2304) = X(18432x768) @ [Wq|Wk|Wv]
// Classic 128x128x16 register-tiled SGEMM, 8x8 per thread, 256 threads.
// Each 128-wide N tile lies entirely inside one of Wq/Wk/Wv (768 % 128 == 0).
// ---------------------------------------------------------------------------
#define BM 128
#define BN 128
#define BKk 16
#define TM 8
#define TN 8

__global__ __launch_bounds__(256) void gemm_qkv(
    const float* __restrict__ X,
    const float* __restrict__ Wq, const float* __restrict__ bq,
    const float* __restrict__ Wk, const float* __restrict__ bk,
    const float* __restrict__ Wv, const float* __restrict__ bv)
{
    __shared__ float As[BKk][BM];
    __shared__ float Bs[BKk][BN];

    const int bm = blockIdx.y;
    const int bn = blockIdx.x;
    const int which = (bn * BN) / Dsz;          // 0:q 1:k 2:v
    const float* W    = which == 0 ? Wq : (which == 1 ? Wk : Wv);
    const float* bias = which == 0 ? bq : (which == 1 ? bk : bv);
    float* OUT        = which == 0 ? g_q : (which == 1 ? g_k : g_v);
    const int n0 = bn * BN - which * Dsz;       // local column offset within W
    const int m0 = bm * BM;

    const int tid = threadIdx.x;
    const int tx = tid % 16;
    const int ty = tid / 16;

    float acc[TM][TN];
    #pragma unroll
    for (int i = 0; i < TM; i++)
        #pragma unroll
        for (int j = 0; j < TN; j++) acc[i][j] = 0.f;

    for (int k0 = 0; k0 < Dsz; k0 += BKk) {
        // A tile: 128 rows x 16 cols -> As[k][m]   (512 float4, 2 per thread)
        #pragma unroll
        for (int j = 0; j < 2; j++) {
            int f = tid + 256 * j;
            int r = f >> 2, c4 = f & 3;
            float4 a = *(const float4*)&X[(size_t)(m0 + r) * Dsz + k0 + c4 * 4];
            As[c4*4+0][r] = a.x;
            As[c4*4+1][r] = a.y;
            As[c4*4+2][r] = a.z;
            As[c4*4+3][r] = a.w;
        }
        // B tile: 16 rows x 128 cols
        #pragma unroll
        for (int j = 0; j < 2; j++) {
            int f = tid + 256 * j;
            int r = f >> 5, c4 = f & 31;
            *(float4*)&Bs[r][c4*4] =
                *(const float4*)&W[(size_t)(k0 + r) * Dsz + n0 + c4 * 4];
        }
        __syncthreads();
        #pragma unroll
        for (int k = 0; k < BKk; k++) {
            float a[TM], b[TN];
            #pragma unroll
            for (int i = 0; i < TM; i++) a[i] = As[k][ty*TM + i];
            #pragma unroll
            for (int j = 0; j < TN; j++) b[j] = Bs[k][tx*TN + j];
            #pragma unroll
            for (int i = 0; i < TM; i++)
                #pragma unroll
                for (int j = 0; j < TN; j++)
                    acc[i][j] = fmaf(a[i], b[j], acc[i][j]);
        }
        __syncthreads();
    }

    #pragma unroll
    for (int i = 0; i < TM; i++) {
        int gm = m0 + ty*TM + i;
        #pragma unroll
        for (int j = 0; j < TN; j += 4) {
            int gn = n0 + tx*TN + j;
            float4 r;
            r.x = acc[i][j+0] + bias[gn+0];
            r.y = acc[i][j+1] + bias[gn+1];
            r.z = acc[i][j+2] + bias[gn+2];
            r.w = acc[i][j+3] + bias[gn+3];
            *(float4*)&OUT[(size_t)gm * Dsz + gn] = r;
        }
    }
}

// ---------------------------------------------------------------------------
// Kernel 2: key_finder_net. 128 rows per block; fc1 (1536->60, weights staged
// through smem in 32-deep K chunks), fc2 (60->60), fc3 (60->2) + tanh.
// Static smem kept < 48KB via region aliasing (fc1 tiles die before H lives).
// ---------------------------------------------------------------------------
__global__ __launch_bounds__(256) void mlp_kernel(
    const float* __restrict__ W1, const float* __restrict__ b1,
    const float* __restrict__ W2, const float* __restrict__ b2,
    const float* __restrict__ W3, const float* __restrict__ b3)
{
    __shared__ float smem[11776];  // 46.06 KB
    float (*As)[128] = (float(*)[128])smem;          // [32][128] fc1 A^T tile
    float (*Ws)[64]  = (float(*)[64])(smem + 4096);  // [32][64]  fc1 W tile
    float (*H)[128]  = (float(*)[128])smem;          // [60][128] h^T (aliases As/Ws)
    float (*W2s)[64] = (float(*)[64])(smem + 7680);  // [60][64]
    float *W3s = smem + 11520;                        // [120]
    float *b3s = smem + 11640;                        // [2]

    const int tid = threadIdx.x;
    const int tx = tid % 16;     // output cols tx*4 .. tx*4+3 (padded to 64)
    const int ty = tid / 16;     // rows ty*8 .. ty*8+7
    const int row0 = blockIdx.x * 128;

    float acc[8][4];
    #pragma unroll
    for (int r = 0; r < 8; r++)
        #pragma unroll
        for (int j = 0; j < 4; j++) {
            int o = tx*4 + j;
            acc[r][j] = (o < 60) ? b1[o] : 0.f;
        }

    for (int kc = 0; kc < 2*Dsz; kc += 32) {
        const float* src = (kc < Dsz) ? g_q : g_k;   // concat(q,k) on the fly
        const int coff = (kc < Dsz) ? kc : kc - Dsz;
        #pragma unroll
        for (int j = 0; j < 4; j++) {
            int f = tid + 256 * j;        // 1024 float4 total
            int r = f >> 3, c4 = f & 7;
            float4 a = *(const float4*)&src[(size_t)(row0 + r) * Dsz + coff + c4*4];
            As[c4*4+0][r] = a.x;
            As[c4*4+1][r] = a.y;
            As[c4*4+2][r] = a.z;
            As[c4*4+3][r] = a.w;
        }
        for (int e = tid; e < 32*64; e += 256) {
            int i = e >> 6, o = e & 63;
            Ws[i][o] = (o < 60) ? W1[(size_t)(kc + i) * 60 + o] : 0.f;
        }
        __syncthreads();
        #pragma unroll
        for (int i = 0; i < 32; i++) {
            float4 w = *(const float4*)&Ws[i][tx*4];
            float a[8];
            #pragma unroll
            for (int r = 0; r < 8; r++) a[r] = As[i][ty*8 + r];
            #pragma unroll
            for (int r = 0; r < 8; r++) {
                acc[r][0] = fmaf(a[r], w.x, acc[r][0]);
                acc[r][1] = fmaf(a[r], w.y, acc[r][1]);
                acc[r][2] = fmaf(a[r], w.z, acc[r][2]);
                acc[r][3] = fmaf(a[r], w.w, acc[r][3]);
            }
        }
        __syncthreads();
    }

    // relu -> H[o][r]  (H aliases dead As/Ws; safe after the sync above)
    #pragma unroll
    for (int r = 0; r < 8; r++)
        #pragma unroll
        for (int j = 0; j < 4; j++) {
            int o = tx*4 + j;
            if (o < 60) H[o][ty*8 + r] = fmaxf(acc[r][j], 0.f);
        }
    for (int e = tid; e < 60*64; e += 256) {
        int i = e >> 6, o = e & 63;
        W2s[i][o] = (o < 60) ? W2[i*60 + o] : 0.f;
    }
    if (tid < 120) W3s[tid] = W3[tid];
    if (tid < 2)   b3s[tid] = b3[tid];
    __syncthreads();

    // fc2
    float acc2[8][4];
    #pragma unroll
    for (int r = 0; r < 8; r++)
        #pragma unroll
        for (int j = 0; j < 4; j++) {
            int o = tx*4 + j;
            acc2[r][j] = (o < 60) ? b2[o] : 0.f;
        }
    #pragma unroll 4
    for (int i = 0; i < 60; i++) {
        float4 w = *(const float4*)&W2s[i][tx*4];
        float a[8];
        #pragma unroll
        for (int r = 0; r < 8; r++) a[r] = H[i][ty*8 + r];
        #pragma unroll
        for (int r = 0; r < 8; r++) {
            acc2[r][0] = fmaf(a[r], w.x, acc2[r][0]);
            acc2[r][1] = fmaf(a[r], w.y, acc2[r][1]);
            acc2[r][2] = fmaf(a[r], w.z, acc2[r][2]);
            acc2[r][3] = fmaf(a[r], w.w, acc2[r][3]);
        }
    }
    __syncthreads();
    #pragma unroll
    for (int r = 0; r < 8; r++)
        #pragma unroll
        for (int j = 0; j < 4; j++) {
            int o = tx*4 + j;
            if (o < 60) H[o][ty*8 + r] = fmaxf(acc2[r][j], 0.f);
        }
    __syncthreads();

    // fc3 + tanh, one row per thread (threads 0..127)
    if (tid < 128) {
        float s0 = b3s[0], s1 = b3s[1];
        #pragma unroll 4
        for (int i = 0; i < 60; i++) {
            float h = H[i][tid];
            s0 = fmaf(h, W3s[i*2 + 0], s0);
            s1 = fmaf(h, W3s[i*2 + 1], s1);
        }
        size_t rr = (size_t)(row0 + tid) * 2;
        g_sample[rr + 0] = tanhf(s0);
        g_sample[rr + 1] = tanhf(s1);
    }
}

// ---------------------------------------------------------------------------
// Kernel 3: grid construction + bilinear sample (zeros padding, align=False)
// + score dot + sigmoid gate + output.  One block per output row (b,s).
// ---------------------------------------------------------------------------
__global__ __launch_bounds__(256) void sample_attn_kernel(float* __restrict__ out)
{
    const int row = blockIdx.x;            // b*576 + s
    const int b = row / Ssz;
    const int s = row % Ssz;
    const int tid = threadIdx.x;

    // flat = concat(sample_x[b,:], sample_y[b,:]); grid coords at flat[2s], flat[2s+1]
    const size_t sbase = (size_t)b * Ssz * 2;
    const int p0 = 2*s, p1 = 2*s + 1;
    const float gxv = (p0 < Ssz) ? g_sample[sbase + (size_t)p0*2 + 0]
                                 : g_sample[sbase + (size_t)(p0 - Ssz)*2 + 1];
    const float gyv = (p1 < Ssz) ? g_sample[sbase + (size_t)p1*2 + 0]
                                 : g_sample[sbase + (size_t)(p1 - Ssz)*2 + 1];

    const float ix = ((gxv + 1.f) * (float)Gsz - 1.f) * 0.5f;
    const float iy = ((gyv + 1.f) * (float)Gsz - 1.f) * 0.5f;
    const float x0f = floorf(ix), y0f = floorf(iy);
    const float wx1 = ix - x0f, wx0 = 1.f - wx1;
    const float wy1 = iy - y0f, wy0 = 1.f - wy1;
    const int x0 = (int)x0f, y0 = (int)y0f;
    const int x1 = x0 + 1,   y1 = y0 + 1;

    float w[4];
    int   pos[4];
    {
        const int xs[4] = {x0, x1, x0, x1};
        const int ys[4] = {y0, y0, y1, y1};
        const float ws[4] = {wx0*wy0, wx1*wy0, wx0*wy1, wx1*wy1};
        #pragma unroll
        for (int c = 0; c < 4; c++) {
            bool v = (xs[c] >= 0) && (xs[c] <= Gsz-1) && (ys[c] >= 0) && (ys[c] <= Gsz-1);
            int xc = min(max(xs[c], 0), Gsz-1);
            int yc = min(max(ys[c], 0), Gsz-1);
            pos[c] = yc * Gsz + xc;        // sequence index in the 24x24 image
            w[c] = v ? ws[c] : 0.f;
        }
    }

    const float* qrow = g_q + (size_t)row * Dsz;
    const float* kb   = g_k + (size_t)b * Ssz * Dsz;
    const float* vb   = g_v + (size_t)b * Ssz * Dsz;

    float sv[3];
    float part = 0.f;
    #pragma unroll
    for (int j = 0; j < 3; j++) {
        const int d = tid + j * 256;
        float sk = 0.f, svv = 0.f;
        #pragma unroll
        for (int c = 0; c < 4; c++) {
            sk  = fmaf(w[c], kb[(size_t)pos[c] * Dsz + d], sk);
            svv = fmaf(w[c], vb[(size_t)pos[c] * Dsz + d], svv);
        }
        part = fmaf(qrow[d], sk, part);
        sv[j] = svv;
    }

    __shared__ float red[8];
    __shared__ float gbro;
    #pragma unroll
    for (int o = 16; o > 0; o >>= 1)
        part += __shfl_xor_sync(0xffffffffu, part, o);
    if ((tid & 31) == 0) red[tid >> 5] = part;
    __syncthreads();
    if (tid == 0) {
        float sc = 0.f;
        #pragma unroll
        for (int i = 0; i < 8; i++) sc += red[i];
        gbro = 1.f / (1.f + expf(-0.01f * sc));
    }
    __syncthreads();
    const float g = gbro;

    #pragma unroll
    for (int j = 0; j < 3; j++) {
        const int d = tid + j * 256;
        out[(size_t)row * Dsz + d] = g * sv[j];
    }
}

// ---------------------------------------------------------------------------
extern "C" void kernel_launch(void* const* d_in, const int* in_sizes, int n_in,
                              void* d_out, int out_size)
{
    const float* x  = (const float*)d_in[0];
    // d_in[1] = indices (unused by the reference)
    const float* Wq = (const float*)d_in[2];
    const float* bq = (const float*)d_in[3];
    const float* Wk = (const float*)d_in[4];
    const float* bk = (const float*)d_in[5];
    const float* Wv = (const float*)d_in[6];
    const float* bv = (const float*)d_in[7];
    const float* W1 = (const float*)d_in[8];
    const float* b1 = (const float*)d_in[9];
    const float* W2 = (const float*)d_in[10];
    const float* b2 = (const float*)d_in[11];
    const float* W3 = (const float*)d_in[12];
    const float* b3 = (const float*)d_in[13];

    dim3 g1(3 * Dsz / BN, Mrows / BM);   // (18, 144)
    gemm_qkv<<<g1, 256>>>(x, Wq, bq, Wk, bk, Wv, bv);
    mlp_kernel<<<Mrows / 128, 256>>>(W1, b1, W2, b2, W3, b3);
    sample_attn_kernel<<<Mrows, 256>>>((float*)d_out);
}

// round 3
// speedup vs baseline: 2.0112x; 2.0112x over previous
#include <cuda_runtime.h>
#include <cuda_bf16.h>
#include <math.h>
#include <cstdint>

#define Bsz 32
#define Ssz 576
#define Dsz 768
#define Gsz 24
#define Mrows (Bsz*Ssz)   // 18432
#define Ncols (3*Dsz)     // 2304

// ---------------- device scratch (allocation-free rule) ----------------
__device__ float g_q[Mrows*Dsz];
__device__ float g_k[Mrows*Dsz];
__device__ float g_v[Mrows*Dsz];
__device__ float g_sample[Mrows*2];
__device__ __nv_bfloat16 g_xhi[Mrows*Dsz];
__device__ __nv_bfloat16 g_xlo[Mrows*Dsz];
__device__ __nv_bfloat16 g_wthi[Ncols*Dsz];   // W^T [n][k]
__device__ __nv_bfloat16 g_wtlo[Ncols*Dsz];

__device__ __forceinline__ uint32_t smem_u32(const void* p) {
    uint32_t a;
    asm("{ .reg .u64 t; cvta.to.shared.u64 t, %1; cvt.u32.u64 %0, t; }" : "=r"(a) : "l"(p));
    return a;
}
__device__ __forceinline__ void cpa16(uint32_t d, const void* s) {
    asm volatile("cp.async.cg.shared.global [%0], [%1], 16;" :: "r"(d), "l"(s));
}
#define CP_COMMIT() asm volatile("cp.async.commit_group;" ::: "memory")
#define CP_WAIT(n)  asm volatile("cp.async.wait_group %0;" :: "n"(n) : "memory")

#define MMA16816(c, A, B) \
    asm volatile("mma.sync.aligned.m16n8k16.row.col.f32.bf16.bf16.f32 " \
        "{%0,%1,%2,%3},{%4,%5,%6,%7},{%8,%9},{%0,%1,%2,%3};" \
        : "+f"((c)[0]), "+f"((c)[1]), "+f"((c)[2]), "+f"((c)[3]) \
        : "r"((A)[0]), "r"((A)[1]), "r"((A)[2]), "r"((A)[3]), "r"((B)[0]), "r"((B)[1]))

// ---------------------------------------------------------------------------
// Prep 1: X fp32 -> bf16 hi/lo
// ---------------------------------------------------------------------------
__global__ __launch_bounds__(256) void prep_x(const float* __restrict__ X)
{
    const int t = blockIdx.x * 256 + threadIdx.x;
    const size_t base = (size_t)t * 8;
    float4 a = *(const float4*)&X[base];
    float4 b = *(const float4*)&X[base + 4];
    __nv_bfloat16 hi[8], lo[8];
    float v[8] = {a.x,a.y,a.z,a.w,b.x,b.y,b.z,b.w};
    #pragma unroll
    for (int i = 0; i < 8; i++) {
        hi[i] = __float2bfloat16(v[i]);
        lo[i] = __float2bfloat16(v[i] - __bfloat162float(hi[i]));
    }
    *(uint4*)&g_xhi[base] = *(uint4*)hi;
    *(uint4*)&g_xlo[base] = *(uint4*)lo;
}

// ---------------------------------------------------------------------------
// Prep 2: W [k][n] fp32 -> Wt hi/lo [n][k] bf16 (32x32 smem transpose)
// ---------------------------------------------------------------------------
__global__ __launch_bounds__(256) void prep_w(
    const float* __restrict__ Wq, const float* __restrict__ Wk, const float* __restrict__ Wv)
{
    __shared__ float ts[32][33];
    const int bx = blockIdx.x;              // n tile 0..71
    const int by = blockIdx.y;              // k tile 0..23
    const int which = bx / 24;
    const float* W = which == 0 ? Wq : (which == 1 ? Wk : Wv);
    const int nloc0 = (bx % 24) * 32;
    const int k0 = by * 32;
    const int tx = threadIdx.x % 32, ty = threadIdx.x / 32;

    #pragma unroll
    for (int r = ty; r < 32; r += 8)
        ts[r][tx] = W[(size_t)(k0 + r) * Dsz + nloc0 + tx];
    __syncthreads();
    #pragma unroll
    for (int r = ty; r < 32; r += 8) {
        float v = ts[tx][r];
        __nv_bfloat16 hi = __float2bfloat16(v);
        __nv_bfloat16 lo = __float2bfloat16(v - __bfloat162float(hi));
        size_t o = (size_t)(bx * 32 + r) * Dsz + k0 + tx;
        g_wthi[o] = hi;
        g_wtlo[o] = lo;
    }
}

// ---------------------------------------------------------------------------
// Kernel 1: QKV GEMM on mma.sync (HMMA) bf16x3.
// Block tile 256(M) x 128(N), 512 threads = 16 warps (4x4), warp tile 64x32.
// K chunks of 32, double-buffered cp.async. Rows padded to 40 bf16 (80B =
// 20-bank stride -> conflict-free fragment LDS).
// Stage layout (bytes): Ah[0,20480) Al[20480,40960) Bh[40960,51200) Bl[51200,61440)
// ---------------------------------------------------------------------------
#define GBM 256
#define GBN 128
#define KC 32
#define PADR 40
#define STAGE_BYTES 61440
#define SMEM_GEMM (2*STAGE_BYTES)

__device__ __forceinline__ void load_chunk_g(uint32_t sb, int stage, int m0, int ng,
                                             int kk, int tid)
{
    const uint32_t s0 = sb + stage * STAGE_BYTES;
    #pragma unroll
    for (int it = 0; it < 2; it++) {
        int f = tid + it * 512;              // 0..1023  (A: 256 rows x 4 units)
        int r = f >> 2, j = f & 3;
        size_t go = (size_t)(m0 + r) * Dsz + kk + j * 8;
        uint32_t dst = s0 + (uint32_t)(r * PADR + j * 8) * 2;
        cpa16(dst,          &g_xhi[go]);
        cpa16(dst + 20480u, &g_xlo[go]);
    }
    {
        int f = tid;                          // 0..511   (B: 128 rows x 4 units)
        int r = f >> 2, j = f & 3;
        size_t go = (size_t)(ng + r) * Dsz + kk + j * 8;
        uint32_t dst = s0 + 40960u + (uint32_t)(r * PADR + j * 8) * 2;
        cpa16(dst,          &g_wthi[go]);
        cpa16(dst + 10240u, &g_wtlo[go]);
    }
}

__global__ __launch_bounds__(512, 1) void gemm_qkv_mma(
    const float* __restrict__ bq, const float* __restrict__ bk, const float* __restrict__ bv)
{
    extern __shared__ char smem[];
    const uint32_t sb = smem_u32(smem);
    const int tid = threadIdx.x;
    const int wid = tid >> 5, lane = tid & 31;
    const int g = lane >> 2, tig = lane & 3;
    const int wm = wid & 3;        // 4 M warp-rows of 64
    const int wn = wid >> 2;       // 4 N warp-cols of 32
    const int m0 = blockIdx.y * GBM;
    const int ng = blockIdx.x * GBN;

    float acc[4][4][4];
    #pragma unroll
    for (int mt = 0; mt < 4; mt++)
        #pragma unroll
        for (int nt = 0; nt < 4; nt++)
            #pragma unroll
            for (int e = 0; e < 4; e++) acc[mt][nt][e] = 0.f;

    load_chunk_g(sb, 0, m0, ng, 0, tid);
    CP_COMMIT();

    const int arow = wm * 64 + g;
    const int brow = wn * 32 + g;

    #pragma unroll 1
    for (int c = 0; c < 24; c++) {
        if (c + 1 < 24) {
            load_chunk_g(sb, (c + 1) & 1, m0, ng, (c + 1) * KC, tid);
            CP_COMMIT();
            CP_WAIT(1);
        } else {
            CP_WAIT(0);
        }
        __syncthreads();

        const char* base = smem + (c & 1) * STAGE_BYTES;
        const __nv_bfloat16* Ah = (const __nv_bfloat16*)(base);
        const __nv_bfloat16* Al = (const __nv_bfloat16*)(base + 20480);
        const __nv_bfloat16* Bh = (const __nv_bfloat16*)(base + 40960);
        const __nv_bfloat16* Bl = (const __nv_bfloat16*)(base + 51200);

        #pragma unroll
        for (int ks = 0; ks < KC; ks += 16) {
            uint32_t af[4][4], bfr[4][2];
            // --- Ahi frags ---
            #pragma unroll
            for (int mt = 0; mt < 4; mt++) {
                const int r0 = arow + mt * 16;
                af[mt][0] = *(const uint32_t*)&Ah[(r0    ) * PADR + ks     + tig*2];
                af[mt][1] = *(const uint32_t*)&Ah[(r0 + 8) * PADR + ks     + tig*2];
                af[mt][2] = *(const uint32_t*)&Ah[(r0    ) * PADR + ks + 8 + tig*2];
                af[mt][3] = *(const uint32_t*)&Ah[(r0 + 8) * PADR + ks + 8 + tig*2];
            }
            // --- Bhi frags, product Ahi*Bhi ---
            #pragma unroll
            for (int nt = 0; nt < 4; nt++) {
                const int n = brow + nt * 8;
                bfr[nt][0] = *(const uint32_t*)&Bh[n * PADR + ks     + tig*2];
                bfr[nt][1] = *(const uint32_t*)&Bh[n * PADR + ks + 8 + tig*2];
            }
            #pragma unroll
            for (int mt = 0; mt < 4; mt++)
                #pragma unroll
                for (int nt = 0; nt < 4; nt++) MMA16816(acc[mt][nt], af[mt], bfr[nt]);
            // --- Blo frags, product Ahi*Blo ---
            #pragma unroll
            for (int nt = 0; nt < 4; nt++) {
                const int n = brow + nt * 8;
                bfr[nt][0] = *(const uint32_t*)&Bl[n * PADR + ks     + tig*2];
                bfr[nt][1] = *(const uint32_t*)&Bl[n * PADR + ks + 8 + tig*2];
            }
            #pragma unroll
            for (int mt = 0; mt < 4; mt++)
                #pragma unroll
                for (int nt = 0; nt < 4; nt++) MMA16816(acc[mt][nt], af[mt], bfr[nt]);
            // --- Alo frags + Bhi again, product Alo*Bhi ---
            #pragma unroll
            for (int mt = 0; mt < 4; mt++) {
                const int r0 = arow + mt * 16;
                af[mt][0] = *(const uint32_t*)&Al[(r0    ) * PADR + ks     + tig*2];
                af[mt][1] = *(const uint32_t*)&Al[(r0 + 8) * PADR + ks     + tig*2];
                af[mt][2] = *(const uint32_t*)&Al[(r0    ) * PADR + ks + 8 + tig*2];
                af[mt][3] = *(const uint32_t*)&Al[(r0 + 8) * PADR + ks + 8 + tig*2];
            }
            #pragma unroll
            for (int nt = 0; nt < 4; nt++) {
                const int n = brow + nt * 8;
                bfr[nt][0] = *(const uint32_t*)&Bh[n * PADR + ks     + tig*2];
                bfr[nt][1] = *(const uint32_t*)&Bh[n * PADR + ks + 8 + tig*2];
            }
            #pragma unroll
            for (int mt = 0; mt < 4; mt++)
                #pragma unroll
                for (int nt = 0; nt < 4; nt++) MMA16816(acc[mt][nt], af[mt], bfr[nt]);
        }
        __syncthreads();
    }

    // Epilogue: bias + store fp32
    const int which = ng / Dsz;
    const int nloc0 = ng - which * Dsz;
    const float* bias = which == 0 ? bq : (which == 1 ? bk : bv);
    float* OUT       = which == 0 ? g_q : (which == 1 ? g_k : g_v);

    #pragma unroll
    for (int mt = 0; mt < 4; mt++) {
        const int r0 = m0 + wm * 64 + mt * 16 + g;
        #pragma unroll
        for (int nt = 0; nt < 4; nt++) {
            const int nl = nloc0 + wn * 32 + nt * 8 + tig * 2;
            const float b0 = __ldg(&bias[nl]), b1 = __ldg(&bias[nl + 1]);
            float2 v0 = make_float2(acc[mt][nt][0] + b0, acc[mt][nt][1] + b1);
            float2 v1 = make_float2(acc[mt][nt][2] + b0, acc[mt][nt][3] + b1);
            *(float2*)&OUT[(size_t)r0       * Dsz + nl] = v0;
            *(float2*)&OUT[(size_t)(r0 + 8) * Dsz + nl] = v1;
        }
    }
}

// ---------------------------------------------------------------------------
// Kernel 2: key_finder_net (unchanged, passing)
// ---------------------------------------------------------------------------
__global__ __launch_bounds__(256) void mlp_kernel(
    const float* __restrict__ W1, const float* __restrict__ b1,
    const float* __restrict__ W2, const float* __restrict__ b2,
    const float* __restrict__ W3, const float* __restrict__ b3)
{
    __shared__ float smem[11776];
    float (*As)[128] = (float(*)[128])smem;
    float (*Ws)[64]  = (float(*)[64])(smem + 4096);
    float (*H)[128]  = (float(*)[128])smem;
    float (*W2s)[64] = (float(*)[64])(smem + 7680);
    float *W3s = smem + 11520;
    float *b3s = smem + 11640;

    const int tid = threadIdx.x;
    const int tx = tid % 16;
    const int ty = tid / 16;
    const int row0 = blockIdx.x * 128;

    float acc[8][4];
    #pragma unroll
    for (int r = 0; r < 8; r++)
        #pragma unroll
        for (int j = 0; j < 4; j++) {
            int o = tx*4 + j;
            acc[r][j] = (o < 60) ? b1[o] : 0.f;
        }

    for (int kc = 0; kc < 2*Dsz; kc += 32) {
        const float* src = (kc < Dsz) ? g_q : g_k;
        const int coff = (kc < Dsz) ? kc : kc - Dsz;
        #pragma unroll
        for (int j = 0; j < 4; j++) {
            int f = tid + 256 * j;
            int r = f >> 3, c4 = f & 7;
            float4 a = *(const float4*)&src[(size_t)(row0 + r) * Dsz + coff + c4*4];
            As[c4*4+0][r] = a.x;
            As[c4*4+1][r] = a.y;
            As[c4*4+2][r] = a.z;
            As[c4*4+3][r] = a.w;
        }
        for (int e = tid; e < 32*64; e += 256) {
            int i = e >> 6, o = e & 63;
            Ws[i][o] = (o < 60) ? W1[(size_t)(kc + i) * 60 + o] : 0.f;
        }
        __syncthreads();
        #pragma unroll
        for (int i = 0; i < 32; i++) {
            float4 w = *(const float4*)&Ws[i][tx*4];
            float a[8];
            #pragma unroll
            for (int r = 0; r < 8; r++) a[r] = As[i][ty*8 + r];
            #pragma unroll
            for (int r = 0; r < 8; r++) {
                acc[r][0] = fmaf(a[r], w.x, acc[r][0]);
                acc[r][1] = fmaf(a[r], w.y, acc[r][1]);
                acc[r][2] = fmaf(a[r], w.z, acc[r][2]);
                acc[r][3] = fmaf(a[r], w.w, acc[r][3]);
            }
        }
        __syncthreads();
    }

    #pragma unroll
    for (int r = 0; r < 8; r++)
        #pragma unroll
        for (int j = 0; j < 4; j++) {
            int o = tx*4 + j;
            if (o < 60) H[o][ty*8 + r] = fmaxf(acc[r][j], 0.f);
        }
    for (int e = tid; e < 60*64; e += 256) {
        int i = e >> 6, o = e & 63;
        W2s[i][o] = (o < 60) ? W2[i*60 + o] : 0.f;
    }
    if (tid < 120) W3s[tid] = W3[tid];
    if (tid < 2)   b3s[tid] = b3[tid];
    __syncthreads();

    float acc2[8][4];
    #pragma unroll
    for (int r = 0; r < 8; r++)
        #pragma unroll
        for (int j = 0; j < 4; j++) {
            int o = tx*4 + j;
            acc2[r][j] = (o < 60) ? b2[o] : 0.f;
        }
    #pragma unroll 4
    for (int i = 0; i < 60; i++) {
        float4 w = *(const float4*)&W2s[i][tx*4];
        float a[8];
        #pragma unroll
        for (int r = 0; r < 8; r++) a[r] = H[i][ty*8 + r];
        #pragma unroll
        for (int r = 0; r < 8; r++) {
            acc2[r][0] = fmaf(a[r], w.x, acc2[r][0]);
            acc2[r][1] = fmaf(a[r], w.y, acc2[r][1]);
            acc2[r][2] = fmaf(a[r], w.z, acc2[r][2]);
            acc2[r][3] = fmaf(a[r], w.w, acc2[r][3]);
        }
    }
    __syncthreads();
    #pragma unroll
    for (int r = 0; r < 8; r++)
        #pragma unroll
        for (int j = 0; j < 4; j++) {
            int o = tx*4 + j;
            if (o < 60) H[o][ty*8 + r] = fmaxf(acc2[r][j], 0.f);
        }
    __syncthreads();

    if (tid < 128) {
        float s0 = b3s[0], s1 = b3s[1];
        #pragma unroll 4
        for (int i = 0; i < 60; i++) {
            float h = H[i][tid];
            s0 = fmaf(h, W3s[i*2 + 0], s0);
            s1 = fmaf(h, W3s[i*2 + 1], s1);
        }
        size_t rr = (size_t)(row0 + tid) * 2;
        g_sample[rr + 0] = tanhf(s0);
        g_sample[rr + 1] = tanhf(s1);
    }
}

// ---------------------------------------------------------------------------
// Kernel 3: grid-sample + score + gate (unchanged, passing)
// ---------------------------------------------------------------------------
__global__ __launch_bounds__(256) void sample_attn_kernel(float* __restrict__ out)
{
    const int row = blockIdx.x;
    const int b = row / Ssz;
    const int s = row % Ssz;
    const int tid = threadIdx.x;

    const size_t sbase = (size_t)b * Ssz * 2;
    const int p0 = 2*s, p1 = 2*s + 1;
    const float gxv = (p0 < Ssz) ? g_sample[sbase + (size_t)p0*2 + 0]
                                 : g_sample[sbase + (size_t)(p0 - Ssz)*2 + 1];
    const float gyv = (p1 < Ssz) ? g_sample[sbase + (size_t)p1*2 + 0]
                                 : g_sample[sbase + (size_t)(p1 - Ssz)*2 + 1];

    const float ix = ((gxv + 1.f) * (float)Gsz - 1.f) * 0.5f;
    const float iy = ((gyv + 1.f) * (float)Gsz - 1.f) * 0.5f;
    const float x0f = floorf(ix), y0f = floorf(iy);
    const float wx1 = ix - x0f, wx0 = 1.f - wx1;
    const float wy1 = iy - y0f, wy0 = 1.f - wy1;
    const int x0 = (int)x0f, y0 = (int)y0f;
    const int x1 = x0 + 1,   y1 = y0 + 1;

    float w[4];
    int   pos[4];
    {
        const int xs[4] = {x0, x1, x0, x1};
        const int ys[4] = {y0, y0, y1, y1};
        const float ws[4] = {wx0*wy0, wx1*wy0, wx0*wy1, wx1*wy1};
        #pragma unroll
        for (int c = 0; c < 4; c++) {
            bool v = (xs[c] >= 0) && (xs[c] <= Gsz-1) && (ys[c] >= 0) && (ys[c] <= Gsz-1);
            int xc = min(max(xs[c], 0), Gsz-1);
            int yc = min(max(ys[c], 0), Gsz-1);
            pos[c] = yc * Gsz + xc;
            w[c] = v ? ws[c] : 0.f;
        }
    }

    const float* qrow = g_q + (size_t)row * Dsz;
    const float* kb   = g_k + (size_t)b * Ssz * Dsz;
    const float* vb   = g_v + (size_t)b * Ssz * Dsz;

    float sv[3];
    float part = 0.f;
    #pragma unroll
    for (int j = 0; j < 3; j++) {
        const int d = tid + j * 256;
        float sk = 0.f, svv = 0.f;
        #pragma unroll
        for (int c = 0; c < 4; c++) {
            sk  = fmaf(w[c], kb[(size_t)pos[c] * Dsz + d], sk);
            svv = fmaf(w[c], vb[(size_t)pos[c] * Dsz + d], svv);
        }
        part = fmaf(qrow[d], sk, part);
        sv[j] = svv;
    }

    __shared__ float red[8];
    __shared__ float gbro;
    #pragma unroll
    for (int o = 16; o > 0; o >>= 1)
        part += __shfl_xor_sync(0xffffffffu, part, o);
    if ((tid & 31) == 0) red[tid >> 5] = part;
    __syncthreads();
    if (tid == 0) {
        float sc = 0.f;
        #pragma unroll
        for (int i = 0; i < 8; i++) sc += red[i];
        gbro = 1.f / (1.f + expf(-0.01f * sc));
    }
    __syncthreads();
    const float g = gbro;

    #pragma unroll
    for (int j = 0; j < 3; j++) {
        const int d = tid + j * 256;
        out[(size_t)row * Dsz + d] = g * sv[j];
    }
}

// ---------------------------------------------------------------------------
extern "C" void kernel_launch(void* const* d_in, const int* in_sizes, int n_in,
                              void* d_out, int out_size)
{
    const float* x  = (const float*)d_in[0];
    const float* Wq = (const float*)d_in[2];
    const float* bq = (const float*)d_in[3];
    const float* Wk = (const float*)d_in[4];
    const float* bk = (const float*)d_in[5];
    const float* Wv = (const float*)d_in[6];
    const float* bv = (const float*)d_in[7];
    const float* W1 = (const float*)d_in[8];
    const float* b1 = (const float*)d_in[9];
    const float* W2 = (const float*)d_in[10];
    const float* b2 = (const float*)d_in[11];
    const float* W3 = (const float*)d_in[12];
    const float* b3 = (const float*)d_in[13];

    cudaFuncSetAttribute(gemm_qkv_mma, cudaFuncAttributeMaxDynamicSharedMemorySize, SMEM_GEMM);

    prep_x<<<Mrows * Dsz / (256 * 8), 256>>>(x);
    prep_w<<<dim3(72, 24), 256>>>(Wq, Wk, Wv);
    gemm_qkv_mma<<<dim3(Ncols / GBN, Mrows / GBM), 512, SMEM_GEMM>>>(bq, bk, bv);
    mlp_kernel<<<Mrows / 128, 256>>>(W1, b1, W2, b2, W3, b3);
    sample_attn_kernel<<<Mrows, 256>>>((float*)d_out);
}